// round 5
// baseline (speedup 1.0000x reference)
#include <cuda_runtime.h>
#include <math.h>

// ---------------------------------------------------------------------------
// HyperGraphEncoder — fp32, FFMA2 GEMMs + fused per-step GRU (GEMM+gate)
// ---------------------------------------------------------------------------

typedef unsigned long long ull;

namespace {
constexpr int NB   = 256;
constexpr int HD   = 256;
constexpr int NHEAD = 4;
constexpr int DKH  = 64;
constexpr int TNA  = 127;
constexpr int TNP  = 23;
constexpr int TNH  = 11;
constexpr int G3   = 768;
}

// -------------------------- device scratch ---------------------------------
__device__ float g_atom_f [NB*TNA*HD];
__device__ float g_pharm_f[NB*TNP*HD];
__device__ float g_hyper_f[NB*TNH*HD];
__device__ float g_q1 [NB*TNP*HD];
__device__ float g_k1 [NB*TNH*HD];
__device__ float g_v1 [NB*TNH*HD];
__device__ float g_o1 [NB*TNP*HD];
__device__ float g_pharm2[NB*TNP*HD];
__device__ float g_q2 [NB*TNA*HD];
__device__ float g_k2 [NB*TNP*HD];
__device__ float g_v2 [NB*TNP*HD];
__device__ float g_o2 [NB*TNA*HD];
__device__ float g_h  [NB*TNA*HD];
__device__ float g_gi_f[(size_t)NB*TNA*G3];
__device__ float g_gi_b[(size_t)NB*TNA*G3];
__device__ float g_hcur[2*NB*HD];     // [dir][b][j]
__device__ float g_outsum[2*NB*HD];
__device__ int   g_starts[3*(NB+1)];

// -------------------------- f32x2 helpers -----------------------------------
__device__ __forceinline__ ull pk2(float x) {
    ull r; asm("mov.b64 %0,{%1,%1};" : "=l"(r) : "f"(x)); return r;
}
__device__ __forceinline__ void fma2(ull& d, ull a, ull b) {
    asm("fma.rn.f32x2 %0,%1,%2,%0;" : "+l"(d) : "l"(a), "l"(b));
}
__device__ __forceinline__ void unpk2(ull v, float& lo, float& hi) {
    asm("mov.b64 {%0,%1},%2;" : "=f"(lo), "=f"(hi) : "l"(v));
}

// -------------------------- prefix sums ------------------------------------
__global__ void prefix_kernel(const int* __restrict__ ac,
                              const int* __restrict__ pc,
                              const int* __restrict__ hc) {
    int w = threadIdx.x;
    if (w < 3) {
        const int* c = (w == 0) ? ac : (w == 1) ? pc : hc;
        int* s = (int*)(g_starts + w * (NB + 1));
        int acc = 0;
        for (int i = 0; i < NB; i++) { s[i] = acc; acc += c[i]; }
        s[NB] = acc;
    }
}

// -------------------------- gather / zero-pad -------------------------------
__global__ void gather_kernel(const float* __restrict__ msg,
                              const int* __restrict__ counts,
                              int which, float* __restrict__ out, int maxN) {
    int j = blockIdx.x, b = blockIdx.y;
    int cnt = counts[b];
    float4* dst = (float4*)(out + ((size_t)b * maxN + j) * HD);
    if (j < cnt) {
        int src_row = g_starts[which * (NB + 1) + b] + j;
        const float4* src = (const float4*)(msg + (size_t)src_row * HD);
        dst[threadIdx.x] = src[threadIdx.x];
    } else {
        dst[threadIdx.x] = make_float4(0.f, 0.f, 0.f, 0.f);
    }
}

// -------------------------- FFMA2 SGEMM (64M x 128N tile, BK=16) -------------
template <bool TRANSB>
__global__ void __launch_bounds__(256)
sgemm2_kernel(const float* __restrict__ A, const float* __restrict__ Bm,
              const float* __restrict__ bias, const float* __restrict__ resid,
              float* __restrict__ C, int M, int N, int K) {
    __shared__ float As[16][64];
    __shared__ float Bs[16][128];
    int m0 = blockIdx.y * 64, n0 = blockIdx.x * 128;
    int tid = threadIdx.x;
    int tx = tid & 15, ty = tid >> 4;
    ull acc[4][4] = {};
    for (int k0 = 0; k0 < K; k0 += 16) {
        {
            int row = tid >> 2, seg = tid & 3;
            float4 a = *(const float4*)&A[(size_t)(m0 + row) * K + k0 + seg * 4];
            As[seg*4+0][row] = a.x; As[seg*4+1][row] = a.y;
            As[seg*4+2][row] = a.z; As[seg*4+3][row] = a.w;
        }
        if (!TRANSB) {
            int row = tid >> 4, cs = tid & 15;
            *(float4*)&Bs[row][cs*8]     = *(const float4*)&Bm[(size_t)(k0 + row) * N + n0 + cs*8];
            *(float4*)&Bs[row][cs*8 + 4] = *(const float4*)&Bm[(size_t)(k0 + row) * N + n0 + cs*8 + 4];
        } else {
            int n = tid >> 1, seg = tid & 1;
            float4 b0 = *(const float4*)&Bm[(size_t)(n0 + n) * K + k0 + seg*8];
            float4 b1 = *(const float4*)&Bm[(size_t)(n0 + n) * K + k0 + seg*8 + 4];
            Bs[seg*8+0][n] = b0.x; Bs[seg*8+1][n] = b0.y;
            Bs[seg*8+2][n] = b0.z; Bs[seg*8+3][n] = b0.w;
            Bs[seg*8+4][n] = b1.x; Bs[seg*8+5][n] = b1.y;
            Bs[seg*8+6][n] = b1.z; Bs[seg*8+7][n] = b1.w;
        }
        __syncthreads();
#pragma unroll
        for (int k = 0; k < 16; k++) {
            float4 av = *(const float4*)&As[k][ty * 4];
            ull a0 = pk2(av.x), a1 = pk2(av.y), a2 = pk2(av.z), a3 = pk2(av.w);
            const ulonglong2* bp = (const ulonglong2*)&Bs[k][tx * 8];
            ulonglong2 b01 = bp[0], b23 = bp[1];
            fma2(acc[0][0], a0, b01.x); fma2(acc[0][1], a0, b01.y);
            fma2(acc[0][2], a0, b23.x); fma2(acc[0][3], a0, b23.y);
            fma2(acc[1][0], a1, b01.x); fma2(acc[1][1], a1, b01.y);
            fma2(acc[1][2], a1, b23.x); fma2(acc[1][3], a1, b23.y);
            fma2(acc[2][0], a2, b01.x); fma2(acc[2][1], a2, b01.y);
            fma2(acc[2][2], a2, b23.x); fma2(acc[2][3], a2, b23.y);
            fma2(acc[3][0], a3, b01.x); fma2(acc[3][1], a3, b01.y);
            fma2(acc[3][2], a3, b23.x); fma2(acc[3][3], a3, b23.y);
        }
        __syncthreads();
    }
#pragma unroll
    for (int i = 0; i < 4; i++) {
        int m = m0 + ty * 4 + i;
#pragma unroll
        for (int p = 0; p < 4; p++) {
            int n = n0 + tx * 8 + p * 2;
            float lo, hi;
            unpk2(acc[i][p], lo, hi);
            if (bias)  { lo += bias[n]; hi += bias[n + 1]; }
            if (resid) { float2 rv = *(const float2*)&resid[(size_t)m * N + n];
                         lo += rv.x; hi += rv.y; }
            float2 o; o.x = lo; o.y = hi;
            *(float2*)&C[(size_t)m * N + n] = o;
        }
    }
}

// -------------------------- attention ---------------------------------------
template <int LQ, int LK>
__global__ void attn_kernel(const float* __restrict__ qh,
                            const float* __restrict__ kh,
                            const float* __restrict__ vh,
                            const int* __restrict__ qc,
                            const int* __restrict__ kc,
                            float* __restrict__ o) {
    __shared__ float ks[LK * DKH];
    __shared__ float vs[LK * DKH];
    int bh = blockIdx.x;
    int b = bh / NHEAD, hd = bh % NHEAD;
    for (int idx = threadIdx.x; idx < LK * DKH; idx += blockDim.x) {
        int k = idx / DKH, i = idx % DKH;
        size_t base = ((size_t)(b * LK) + k) * HD + hd * DKH + i;
        ks[idx] = kh[base];
        vs[idx] = vh[base];
    }
    __syncthreads();
    int q = threadIdx.x;
    if (q >= LQ) return;

    float qreg[DKH];
    const float* qp = &qh[((size_t)(b * LQ) + q) * HD + hd * DKH];
#pragma unroll
    for (int i = 0; i < DKH; i++) qreg[i] = qp[i];

    bool vq = q < qc[b];
    int kcnt = kc[b];
    float s[LK];
    float mx = -3.402823e38f;
#pragma unroll
    for (int k = 0; k < LK; k++) {
        float d = 0.f;
#pragma unroll
        for (int i = 0; i < DKH; i++) d = fmaf(qreg[i], ks[k * DKH + i], d);
        float val = (vq && k < kcnt) ? d * 0.125f : -1e9f;
        s[k] = val;
        mx = fmaxf(mx, val);
    }
    float sum = 0.f;
#pragma unroll
    for (int k = 0; k < LK; k++) { s[k] = expf(s[k] - mx); sum += s[k]; }
    float inv = 1.f / sum;
    float* op = &o[((size_t)(b * LQ) + q) * HD + hd * DKH];
#pragma unroll
    for (int i = 0; i < DKH; i++) {
        float a = 0.f;
#pragma unroll
        for (int k = 0; k < LK; k++) a = fmaf(s[k], vs[k * DKH + i], a);
        op[i] = a * inv;
    }
}

// -------------------------- h0 = max over t ---------------------------------
__global__ void hmax_kernel() {
    int b = blockIdx.x, j = threadIdx.x;
    float m = -3.402823e38f;
    for (int t = 0; t < TNA; t++)
        m = fmaxf(m, g_h[((size_t)(b * TNA) + t) * HD + j]);
    g_hcur[(size_t)b * HD + j] = m;
    g_hcur[(size_t)NB * HD + (size_t)b * HD + j] = m;
}

__global__ void zero_outsum_kernel() {
    int idx = blockIdx.x * blockDim.x + threadIdx.x;
    g_outsum[idx] = 0.f;
}

// -------------------------- fused GRU step (GEMM + gate) ---------------------
// grid (4 jt, 16 mt, 2 dir), 256 threads.
// Block computes gh for 16 batches x 64 cols x {r,z,n} (192 N-cols of Whh^T),
// then applies the gate locally: writes hcur, accumulates outsum.
__global__ void __launch_bounds__(256)
gru_step_kernel(const float* __restrict__ Whh_f, const float* __restrict__ Whh_b,
                const float* __restrict__ bhh_f, const float* __restrict__ bhh_b,
                const int* __restrict__ counts, int t) {
    __shared__ float As[16][16];
    __shared__ float Bs[16][192];
    int jt = blockIdx.x, mt = blockIdx.y, gd = blockIdx.z;
    int tid = threadIdx.x;
    int tx = tid & 15, ty = tid >> 4;
    const float* Whh = gd ? Whh_b : Whh_f;
    const float* hcur = g_hcur + (size_t)gd * NB * HD;

    ull acc[3][2] = {};   // gate g, pair of f32x2 covering 4 cols
    for (int k0 = 0; k0 < HD; k0 += 16) {
        {   // A: 16 batches x 16 k — thread (kk = tid&15, bb = tid>>4)
            int kk = tid & 15, bb = tid >> 4;
            As[kk][bb] = hcur[(size_t)(mt * 16 + bb) * HD + k0 + kk];
        }
        {   // B: 192 rows x 16 k; idx = tid + l*256; kseg = idx/192, row = idx%192
#pragma unroll
            for (int l = 0; l < 3; l++) {
                int idx = tid + l * 256;
                int kseg = idx / 192, row = idx - kseg * 192;
                int nrow = jt * 64 + (row & 63) + (row >> 6) * 256;
                float4 bv = *(const float4*)&Whh[(size_t)nrow * HD + k0 + kseg * 4];
                Bs[kseg*4+0][row] = bv.x; Bs[kseg*4+1][row] = bv.y;
                Bs[kseg*4+2][row] = bv.z; Bs[kseg*4+3][row] = bv.w;
            }
        }
        __syncthreads();
#pragma unroll
        for (int k = 0; k < 16; k++) {
            ull a = pk2(As[k][ty]);
#pragma unroll
            for (int g = 0; g < 3; g++) {
                ulonglong2 bv = *(const ulonglong2*)&Bs[k][g * 64 + tx * 4];
                fma2(acc[g][0], a, bv.x);
                fma2(acc[g][1], a, bv.y);
            }
        }
        __syncthreads();
    }

    // ---- gate for batch b = mt*16+ty, cols j = jt*64 + tx*4 .. +3 ----
    int b = mt * 16 + ty;
    int j = jt * 64 + tx * 4;
    int teff = gd ? (TNA - 1 - t) : t;
    const float* gi = (gd ? g_gi_b : g_gi_f) + ((size_t)b * TNA + teff) * G3 + j;
    const float* bhh = gd ? bhh_b : bhh_f;

    float gh[3][4];
#pragma unroll
    for (int g = 0; g < 3; g++) {
        unpk2(acc[g][0], gh[g][0], gh[g][1]);
        unpk2(acc[g][1], gh[g][2], gh[g][3]);
    }
    float4 gir = *(const float4*)&gi[0];
    float4 giz = *(const float4*)&gi[256];
    float4 gin = *(const float4*)&gi[512];
    float4 bhr = *(const float4*)&bhh[j];
    float4 bhz = *(const float4*)&bhh[j + 256];
    float4 bhn = *(const float4*)&bhh[j + 512];

    size_t hidx = (size_t)gd * NB * HD + (size_t)b * HD + j;
    float4 hp = *(float4*)&g_hcur[hidx];

    float irv[4] = {gir.x, gir.y, gir.z, gir.w};
    float izv[4] = {giz.x, giz.y, giz.z, giz.w};
    float inv_[4] = {gin.x, gin.y, gin.z, gin.w};
    float brv[4] = {bhr.x, bhr.y, bhr.z, bhr.w};
    float bzv[4] = {bhz.x, bhz.y, bhz.z, bhz.w};
    float bnv[4] = {bhn.x, bhn.y, bhn.z, bhn.w};
    float hpv[4] = {hp.x, hp.y, hp.z, hp.w};
    float hv[4];
#pragma unroll
    for (int c = 0; c < 4; c++) {
        float r = 1.f / (1.f + expf(-(irv[c] + gh[0][c] + brv[c])));
        float z = 1.f / (1.f + expf(-(izv[c] + gh[1][c] + bzv[c])));
        float n = tanhf(inv_[c] + r * (gh[2][c] + bnv[c]));
        hv[c] = (1.f - z) * n + z * hpv[c];
    }
    float4 ho; ho.x = hv[0]; ho.y = hv[1]; ho.z = hv[2]; ho.w = hv[3];
    *(float4*)&g_hcur[hidx] = ho;

    if (teff < counts[b]) {
        float4 os = *(float4*)&g_outsum[hidx];
        os.x += hv[0]; os.y += hv[1]; os.z += hv[2]; os.w += hv[3];
        *(float4*)&g_outsum[hidx] = os;
    }
}

__global__ void final_kernel(const int* __restrict__ counts, float* __restrict__ out) {
    int idx = blockIdx.x * blockDim.x + threadIdx.x;
    int d = idx >> 16;
    int b = (idx >> 8) & 255;
    int j = idx & 255;
    float c = (float)counts[b];
    out[(size_t)b * 512 + d * 256 + j] =
        g_outsum[(size_t)d * NB * HD + (size_t)b * HD + j] / c;
}

// -------------------------- host launch -------------------------------------
static float* symaddr(const void* sym) {
    void* p = nullptr;
    cudaGetSymbolAddress(&p, sym);
    return (float*)p;
}

extern "C" void kernel_launch(void* const* d_in, const int* in_sizes, int n_in,
                              void* d_out, int out_size) {
    int wbase, ci0, ci1, ci2;
    if (in_sizes[3] == NB) { ci0 = 3; ci1 = 4; ci2 = 5; wbase = 6; }
    else { wbase = 3; ci0 = n_in - 3; ci1 = n_in - 2; ci2 = n_in - 1; }

    const float* atom_msg  = (const float*)d_in[0];
    const float* pharm_msg = (const float*)d_in[1];
    const float* hyper_msg = (const float*)d_in[2];
    const int* ac = (const int*)d_in[ci0];
    const int* pc = (const int*)d_in[ci1];
    const int* hc = (const int*)d_in[ci2];

    const float* p2h[8];
    const float* a2p[8];
    for (int i = 0; i < 8; i++) p2h[i] = (const float*)d_in[wbase + i];
    for (int i = 0; i < 8; i++) a2p[i] = (const float*)d_in[wbase + 8 + i];
    const float* Wih_f = (const float*)d_in[wbase + 16];
    const float* Whh_f = (const float*)d_in[wbase + 17];
    const float* bih_f = (const float*)d_in[wbase + 18];
    const float* bhh_f = (const float*)d_in[wbase + 19];
    const float* Wih_b = (const float*)d_in[wbase + 20];
    const float* Whh_b = (const float*)d_in[wbase + 21];
    const float* bih_b = (const float*)d_in[wbase + 22];
    const float* bhh_b = (const float*)d_in[wbase + 23];

    float* atom_f  = symaddr(g_atom_f);
    float* pharm_f = symaddr(g_pharm_f);
    float* hyper_f = symaddr(g_hyper_f);
    float* q1 = symaddr(g_q1);
    float* k1 = symaddr(g_k1);
    float* v1 = symaddr(g_v1);
    float* o1 = symaddr(g_o1);
    float* pharm2 = symaddr(g_pharm2);
    float* q2 = symaddr(g_q2);
    float* k2 = symaddr(g_k2);
    float* v2 = symaddr(g_v2);
    float* o2 = symaddr(g_o2);
    float* hbuf = symaddr(g_h);
    float* gi_f = symaddr(g_gi_f);
    float* gi_b = symaddr(g_gi_b);

    float* out = (float*)d_out;

    const int MA = NB * TNA;   // 32512
    const int MP = NB * TNP;   // 5888
    const int MH = NB * TNH;   // 2816

    prefix_kernel<<<1, 32>>>(ac, pc, hc);

    gather_kernel<<<dim3(TNA, NB), 64>>>(atom_msg,  ac, 0, atom_f,  TNA);
    gather_kernel<<<dim3(TNP, NB), 64>>>(pharm_msg, pc, 1, pharm_f, TNP);
    gather_kernel<<<dim3(TNH, NB), 64>>>(hyper_msg, hc, 2, hyper_f, TNH);

    // MHA1 (pharm queries, hyper kv)
    sgemm2_kernel<false><<<dim3(HD/128, MP/64), 256>>>(pharm_f, p2h[0], p2h[1], nullptr, q1, MP, HD, HD);
    sgemm2_kernel<false><<<dim3(HD/128, MH/64), 256>>>(hyper_f, p2h[2], p2h[3], nullptr, k1, MH, HD, HD);
    sgemm2_kernel<false><<<dim3(HD/128, MH/64), 256>>>(hyper_f, p2h[4], p2h[5], nullptr, v1, MH, HD, HD);
    attn_kernel<TNP, TNH><<<NB * NHEAD, 32>>>(q1, k1, v1, pc, hc, o1);
    sgemm2_kernel<false><<<dim3(HD/128, MP/64), 256>>>(o1, p2h[6], p2h[7], pharm_f, pharm2, MP, HD, HD);

    // MHA2 (atom queries, updated-pharm kv)
    sgemm2_kernel<false><<<dim3(HD/128, MA/64), 256>>>(atom_f, a2p[0], a2p[1], nullptr, q2, MA, HD, HD);
    sgemm2_kernel<false><<<dim3(HD/128, MP/64), 256>>>(pharm2, a2p[2], a2p[3], nullptr, k2, MP, HD, HD);
    sgemm2_kernel<false><<<dim3(HD/128, MP/64), 256>>>(pharm2, a2p[4], a2p[5], nullptr, v2, MP, HD, HD);
    attn_kernel<TNA, TNP><<<NB * NHEAD, 128>>>(q2, k2, v2, ac, pc, o2);
    sgemm2_kernel<false><<<dim3(HD/128, MA/64), 256>>>(o2, a2p[6], a2p[7], atom_f, hbuf, MA, HD, HD);

    // h0 = max over t (both GRU directions)
    hmax_kernel<<<NB, HD>>>();

    // GRU input precompute gi = h @ Wih^T + bih (per direction)
    sgemm2_kernel<true><<<dim3(G3/128, MA/64), 256>>>(hbuf, Wih_f, bih_f, nullptr, gi_f, MA, G3, HD);
    sgemm2_kernel<true><<<dim3(G3/128, MA/64), 256>>>(hbuf, Wih_b, bih_b, nullptr, gi_b, MA, G3, HD);

    // GRU recurrence: one fused kernel per step
    zero_outsum_kernel<<<(2 * NB * HD) / 256, 256>>>();
    for (int t = 0; t < TNA; t++) {
        gru_step_kernel<<<dim3(4, 16, 2), 256>>>(Whh_f, Whh_b, bhh_f, bhh_b, ac, t);
    }

    final_kernel<<<(2 * NB * HD) / 256, 256>>>(ac, out);
    (void)out_size; (void)n_in;
}

// round 6
// speedup vs baseline: 1.7138x; 1.7138x over previous
#include <cuda_runtime.h>
#include <cuda_bf16.h>
#include <math.h>

// ---------------------------------------------------------------------------
// HyperGraphEncoder — split-bf16 mma.sync GEMMs + per-step GRU
// B=256 graphs, H=256, 4 heads x 64; padded lens: atom 127, pharm 23, hyper 11
// ---------------------------------------------------------------------------

namespace {
constexpr int NB   = 256;
constexpr int HD   = 256;
constexpr int NHEAD = 4;
constexpr int DKH  = 64;
constexpr int TNA  = 127;
constexpr int TNP  = 23;
constexpr int TNH  = 11;
constexpr int G3   = 768;
constexpr int BKP  = 40;   // padded bf16 k-stride (32 + 8): rows 80B, 16B-aligned
}

// -------------------------- device scratch ---------------------------------
__device__ float g_atom_f [NB*TNA*HD];
__device__ float g_pharm_f[NB*TNP*HD];
__device__ float g_hyper_f[NB*TNH*HD];
__device__ float g_q1 [NB*TNP*HD];
__device__ float g_k1 [NB*TNH*HD];
__device__ float g_v1 [NB*TNH*HD];
__device__ float g_o1 [NB*TNP*HD];
__device__ float g_pharm2[NB*TNP*HD];
__device__ float g_q2 [NB*TNA*HD];
__device__ float g_k2 [NB*TNP*HD];
__device__ float g_v2 [NB*TNP*HD];
__device__ float g_o2 [NB*TNA*HD];
__device__ float g_h  [NB*TNA*HD];
__device__ float g_gi_f[(size_t)NB*TNA*G3];
__device__ float g_gi_b[(size_t)NB*TNA*G3];
__device__ float g_hcur[2*NB*HD];     // [dir][b][j]
__device__ float g_gh  [2*NB*G3];     // [dir][b][n]
__device__ float g_outsum[2*NB*HD];
__device__ int   g_starts[3*(NB+1)];

// -------------------------- mma helpers -------------------------------------
__device__ __forceinline__ unsigned s2u(const void* p) {
    return (unsigned)__cvta_generic_to_shared(p);
}
__device__ __forceinline__ void ldmx4(unsigned addr, unsigned& r0, unsigned& r1,
                                      unsigned& r2, unsigned& r3) {
    asm volatile("ldmatrix.sync.aligned.m8n8.x4.shared.b16 {%0,%1,%2,%3}, [%4];"
                 : "=r"(r0), "=r"(r1), "=r"(r2), "=r"(r3) : "r"(addr));
}
__device__ __forceinline__ void mma_bf16(float* c, unsigned a0, unsigned a1,
                                         unsigned a2, unsigned a3,
                                         unsigned b0, unsigned b1) {
    asm volatile(
        "mma.sync.aligned.m16n8k16.row.col.f32.bf16.bf16.f32 "
        "{%0,%1,%2,%3},{%4,%5,%6,%7},{%8,%9},{%0,%1,%2,%3};"
        : "+f"(c[0]), "+f"(c[1]), "+f"(c[2]), "+f"(c[3])
        : "r"(a0), "r"(a1), "r"(a2), "r"(a3), "r"(b0), "r"(b1));
}
__device__ __forceinline__ void split_bf16(float x, __nv_bfloat16& hi, __nv_bfloat16& lo) {
    hi = __float2bfloat16(x);
    lo = __float2bfloat16(x - __bfloat162float(hi));
}

// ---------------------------------------------------------------------------
// split-bf16 GEMM body: C[M,N] = A[M,K] @ B (+bias)(+resid)
// TRANSB: Bm is [N,K] row-major (compute A @ Bm^T); else Bm is [K,N].
// Block tile 128M x 64N, BK=32, 256 threads (8 warps = 4m x 2n of 32x32).
// On-the-fly fp32 -> (hi,lo) bf16 split; acc += Ahi*Bhi + Ahi*Blo + Alo*Bhi.
// ---------------------------------------------------------------------------
template <bool TRANSB>
__device__ __forceinline__ void bgemm_body(
    const float* __restrict__ A, const float* __restrict__ Bm,
    const float* __restrict__ bias, const float* __restrict__ resid,
    float* __restrict__ C, int M, int N, int K, int m0, int n0,
    __nv_bfloat16 (*As)[128][BKP], __nv_bfloat16 (*Bs)[64][BKP]) {

    int tid = threadIdx.x;
    int warp = tid >> 5, lane = tid & 31;
    int wm = (warp & 3) * 32;   // m offset within 128
    int wn = (warp >> 2) * 32;  // n offset within 64

    float acc[2][4][4];
#pragma unroll
    for (int i = 0; i < 2; i++)
#pragma unroll
        for (int j = 0; j < 4; j++)
#pragma unroll
            for (int r = 0; r < 4; r++) acc[i][j][r] = 0.f;

    for (int k0 = 0; k0 < K; k0 += 32) {
        // ---- load + split A tile: 128 x 32 ----
#pragma unroll
        for (int l = 0; l < 4; l++) {
            int idx = tid + l * 256;          // 1024 float4
            int row = idx >> 3, c4 = idx & 7;
            float4 v = *(const float4*)&A[(size_t)(m0 + row) * K + k0 + c4 * 4];
            __nv_bfloat16 h, lo;
            split_bf16(v.x, h, lo); As[0][row][c4*4+0] = h; As[1][row][c4*4+0] = lo;
            split_bf16(v.y, h, lo); As[0][row][c4*4+1] = h; As[1][row][c4*4+1] = lo;
            split_bf16(v.z, h, lo); As[0][row][c4*4+2] = h; As[1][row][c4*4+2] = lo;
            split_bf16(v.w, h, lo); As[0][row][c4*4+3] = h; As[1][row][c4*4+3] = lo;
        }
        // ---- load + split B tile into Bs[n][k] ----
        if (TRANSB) {
#pragma unroll
            for (int l = 0; l < 2; l++) {
                int idx = tid + l * 256;      // 512 float4 (64 rows x 8 f4)
                int row = idx >> 3, c4 = idx & 7;
                float4 v = *(const float4*)&Bm[(size_t)(n0 + row) * K + k0 + c4 * 4];
                __nv_bfloat16 h, lo;
                split_bf16(v.x, h, lo); Bs[0][row][c4*4+0] = h; Bs[1][row][c4*4+0] = lo;
                split_bf16(v.y, h, lo); Bs[0][row][c4*4+1] = h; Bs[1][row][c4*4+1] = lo;
                split_bf16(v.z, h, lo); Bs[0][row][c4*4+2] = h; Bs[1][row][c4*4+2] = lo;
                split_bf16(v.w, h, lo); Bs[0][row][c4*4+3] = h; Bs[1][row][c4*4+3] = lo;
            }
        } else {
#pragma unroll
            for (int l = 0; l < 2; l++) {
                int idx = tid + l * 256;      // 512 float4 (32 k x 16 f4-of-n)
                int k = idx >> 4, f4 = idx & 15;
                float4 v = *(const float4*)&Bm[(size_t)(k0 + k) * N + n0 + f4 * 4];
                __nv_bfloat16 h, lo;
                split_bf16(v.x, h, lo); Bs[0][f4*4+0][k] = h; Bs[1][f4*4+0][k] = lo;
                split_bf16(v.y, h, lo); Bs[0][f4*4+1][k] = h; Bs[1][f4*4+1][k] = lo;
                split_bf16(v.z, h, lo); Bs[0][f4*4+2][k] = h; Bs[1][f4*4+2][k] = lo;
                split_bf16(v.w, h, lo); Bs[0][f4*4+3][k] = h; Bs[1][f4*4+3][k] = lo;
            }
        }
        __syncthreads();

        int r = lane & 15, cg = lane >> 4;
#pragma unroll
        for (int kk = 0; kk < 32; kk += 16) {
            // A fragments (hi/lo) for 2 m16 tiles
            unsigned ah[2][4], al[2][4];
#pragma unroll
            for (int mf = 0; mf < 2; mf++) {
                unsigned addr0 = s2u(&As[0][wm + mf*16 + r][kk + cg*8]);
                ldmx4(addr0, ah[mf][0], ah[mf][1], ah[mf][2], ah[mf][3]);
                unsigned addr1 = s2u(&As[1][wm + mf*16 + r][kk + cg*8]);
                ldmx4(addr1, al[mf][0], al[mf][1], al[mf][2], al[mf][3]);
            }
            // B fragments (hi/lo): 4 n8 frags; each ldmx4 covers 2 of them
            unsigned bh[4][2], bl[4][2];
#pragma unroll
            for (int bf = 0; bf < 2; bf++) {
                unsigned q0, q1, q2, q3;
                unsigned addr0 = s2u(&Bs[0][wn + bf*16 + r][kk + cg*8]);
                ldmx4(addr0, q0, q1, q2, q3);
                bh[bf*2+0][0] = q0; bh[bf*2+1][0] = q1;
                bh[bf*2+0][1] = q2; bh[bf*2+1][1] = q3;
                unsigned addr1 = s2u(&Bs[1][wn + bf*16 + r][kk + cg*8]);
                ldmx4(addr1, q0, q1, q2, q3);
                bl[bf*2+0][0] = q0; bl[bf*2+1][0] = q1;
                bl[bf*2+0][1] = q2; bl[bf*2+1][1] = q3;
            }
#pragma unroll
            for (int mf = 0; mf < 2; mf++)
#pragma unroll
                for (int nf = 0; nf < 4; nf++) {
                    mma_bf16(acc[mf][nf], ah[mf][0], ah[mf][1], ah[mf][2], ah[mf][3],
                             bh[nf][0], bh[nf][1]);
                    mma_bf16(acc[mf][nf], ah[mf][0], ah[mf][1], ah[mf][2], ah[mf][3],
                             bl[nf][0], bl[nf][1]);
                    mma_bf16(acc[mf][nf], al[mf][0], al[mf][1], al[mf][2], al[mf][3],
                             bh[nf][0], bh[nf][1]);
                }
        }
        __syncthreads();
    }

    // ---- epilogue ----
    int g = lane >> 2, tg = lane & 3;
#pragma unroll
    for (int mf = 0; mf < 2; mf++) {
#pragma unroll
        for (int nf = 0; nf < 4; nf++) {
            int c = n0 + wn + nf * 8 + tg * 2;
            int r0 = m0 + wm + mf * 16 + g;
            int r1 = r0 + 8;
            float v0 = acc[mf][nf][0], v1 = acc[mf][nf][1];
            float v2 = acc[mf][nf][2], v3 = acc[mf][nf][3];
            if (bias) { float b0 = bias[c], b1 = bias[c+1]; v0 += b0; v1 += b1; v2 += b0; v3 += b1; }
            if (resid) {
                float2 ra = *(const float2*)&resid[(size_t)r0 * N + c];
                float2 rb = *(const float2*)&resid[(size_t)r1 * N + c];
                v0 += ra.x; v1 += ra.y; v2 += rb.x; v3 += rb.y;
            }
            float2 oa; oa.x = v0; oa.y = v1;
            float2 ob; ob.x = v2; ob.y = v3;
            *(float2*)&C[(size_t)r0 * N + c] = oa;
            *(float2*)&C[(size_t)r1 * N + c] = ob;
        }
    }
}

template <bool TRANSB>
__global__ void __launch_bounds__(256)
bgemm_kernel(const float* __restrict__ A, const float* __restrict__ Bm,
             const float* __restrict__ bias, const float* __restrict__ resid,
             float* __restrict__ C, int M, int N, int K) {
    __shared__ __nv_bfloat16 As[2][128][BKP];
    __shared__ __nv_bfloat16 Bs[2][64][BKP];
    bgemm_body<TRANSB>(A, Bm, bias, resid, C, M, N, K,
                       blockIdx.y * 128, blockIdx.x * 64, As, Bs);
}

// GRU recurrent GEMM: gh[d] = hcur[d] @ Whh_d^T  (M=256, N=768, K=256)
// grid: (12, 2, 2)
__global__ void __launch_bounds__(256)
gru_gh_kernel(const float* __restrict__ Whh_f, const float* __restrict__ Whh_b) {
    __shared__ __nv_bfloat16 As[2][128][BKP];
    __shared__ __nv_bfloat16 Bs[2][64][BKP];
    int d = blockIdx.z;
    bgemm_body<true>(g_hcur + (size_t)d * NB * HD,
                     d ? Whh_b : Whh_f, nullptr, nullptr,
                     g_gh + (size_t)d * NB * G3,
                     NB, G3, HD, blockIdx.y * 128, blockIdx.x * 64, As, Bs);
}

// -------------------------- prefix sums ------------------------------------
__global__ void prefix_kernel(const int* __restrict__ ac,
                              const int* __restrict__ pc,
                              const int* __restrict__ hc) {
    int w = threadIdx.x;
    if (w < 3) {
        const int* c = (w == 0) ? ac : (w == 1) ? pc : hc;
        int* s = (int*)(g_starts + w * (NB + 1));
        int acc = 0;
        for (int i = 0; i < NB; i++) { s[i] = acc; acc += c[i]; }
        s[NB] = acc;
    }
}

// -------------------------- gather / zero-pad -------------------------------
__global__ void gather_kernel(const float* __restrict__ msg,
                              const int* __restrict__ counts,
                              int which, float* __restrict__ out, int maxN) {
    int j = blockIdx.x, b = blockIdx.y;
    int cnt = counts[b];
    float4* dst = (float4*)(out + ((size_t)b * maxN + j) * HD);
    if (j < cnt) {
        int src_row = g_starts[which * (NB + 1) + b] + j;
        const float4* src = (const float4*)(msg + (size_t)src_row * HD);
        dst[threadIdx.x] = src[threadIdx.x];
    } else {
        dst[threadIdx.x] = make_float4(0.f, 0.f, 0.f, 0.f);
    }
}

// -------------------------- attention ---------------------------------------
template <int LQ, int LK>
__global__ void attn_kernel(const float* __restrict__ qh,
                            const float* __restrict__ kh,
                            const float* __restrict__ vh,
                            const int* __restrict__ qc,
                            const int* __restrict__ kc,
                            float* __restrict__ o) {
    __shared__ float ks[LK * DKH];
    __shared__ float vs[LK * DKH];
    int bh = blockIdx.x;
    int b = bh / NHEAD, hd = bh % NHEAD;
    for (int idx = threadIdx.x; idx < LK * DKH; idx += blockDim.x) {
        int k = idx / DKH, i = idx % DKH;
        size_t base = ((size_t)(b * LK) + k) * HD + hd * DKH + i;
        ks[idx] = kh[base];
        vs[idx] = vh[base];
    }
    __syncthreads();
    int q = threadIdx.x;
    if (q >= LQ) return;

    float qreg[DKH];
    const float* qp = &qh[((size_t)(b * LQ) + q) * HD + hd * DKH];
#pragma unroll
    for (int i = 0; i < DKH; i++) qreg[i] = qp[i];

    bool vq = q < qc[b];
    int kcnt = kc[b];
    float s[LK];
    float mx = -3.402823e38f;
#pragma unroll
    for (int k = 0; k < LK; k++) {
        float d = 0.f;
#pragma unroll
        for (int i = 0; i < DKH; i++) d = fmaf(qreg[i], ks[k * DKH + i], d);
        float val = (vq && k < kcnt) ? d * 0.125f : -1e9f;
        s[k] = val;
        mx = fmaxf(mx, val);
    }
    float sum = 0.f;
#pragma unroll
    for (int k = 0; k < LK; k++) { s[k] = expf(s[k] - mx); sum += s[k]; }
    float inv = 1.f / sum;
    float* op = &o[((size_t)(b * LQ) + q) * HD + hd * DKH];
#pragma unroll
    for (int i = 0; i < DKH; i++) {
        float a = 0.f;
#pragma unroll
        for (int k = 0; k < LK; k++) a = fmaf(s[k], vs[k * DKH + i], a);
        op[i] = a * inv;
    }
}

// -------------------------- h0 = max over t ---------------------------------
__global__ void hmax_kernel() {
    int b = blockIdx.x, j = threadIdx.x;
    float m = -3.402823e38f;
    for (int t = 0; t < TNA; t++)
        m = fmaxf(m, g_h[((size_t)(b * TNA) + t) * HD + j]);
    g_hcur[(size_t)b * HD + j] = m;
    g_hcur[(size_t)NB * HD + (size_t)b * HD + j] = m;
}

__global__ void zero_outsum_kernel() {
    int idx = blockIdx.x * blockDim.x + threadIdx.x;
    g_outsum[idx] = 0.f;
}

// -------------------------- GRU gate update ---------------------------------
__global__ void __launch_bounds__(256)
gru_gate_kernel(const float* __restrict__ bhh_f, const float* __restrict__ bhh_b,
                const int* __restrict__ counts, int t) {
    int idx = blockIdx.x * blockDim.x + threadIdx.x;   // 0 .. 2*256*256-1
    int d = idx >> 16;
    int b = (idx >> 8) & 255;
    int j = idx & 255;
    int teff = d ? (TNA - 1 - t) : t;
    const float* gi = (d ? g_gi_b : g_gi_f) + ((size_t)(b * TNA) + teff) * G3;
    const float* bhh = d ? bhh_b : bhh_f;
    const float* gh = g_gh + (size_t)d * NB * G3 + (size_t)b * G3;
    float ir = gi[j], iz = gi[j + 256], in = gi[j + 512];
    float hr = gh[j] + bhh[j];
    float hz = gh[j + 256] + bhh[j + 256];
    float hn = gh[j + 512] + bhh[j + 512];
    float r = 1.f / (1.f + expf(-(ir + hr)));
    float z = 1.f / (1.f + expf(-(iz + hz)));
    float n = tanhf(in + r * hn);
    size_t hidx = (size_t)d * NB * HD + (size_t)b * HD + j;
    float hp = g_hcur[hidx];
    float h = (1.f - z) * n + z * hp;
    g_hcur[hidx] = h;
    if (teff < counts[b]) g_outsum[hidx] += h;
}

__global__ void final_kernel(const int* __restrict__ counts, float* __restrict__ out) {
    int idx = blockIdx.x * blockDim.x + threadIdx.x;
    int d = idx >> 16;
    int b = (idx >> 8) & 255;
    int j = idx & 255;
    float c = (float)counts[b];
    out[(size_t)b * 512 + d * 256 + j] =
        g_outsum[(size_t)d * NB * HD + (size_t)b * HD + j] / c;
}

// -------------------------- host launch -------------------------------------
static float* symaddr(const void* sym) {
    void* p = nullptr;
    cudaGetSymbolAddress(&p, sym);
    return (float*)p;
}

extern "C" void kernel_launch(void* const* d_in, const int* in_sizes, int n_in,
                              void* d_out, int out_size) {
    int wbase, ci0, ci1, ci2;
    if (in_sizes[3] == NB) { ci0 = 3; ci1 = 4; ci2 = 5; wbase = 6; }
    else { wbase = 3; ci0 = n_in - 3; ci1 = n_in - 2; ci2 = n_in - 1; }

    const float* atom_msg  = (const float*)d_in[0];
    const float* pharm_msg = (const float*)d_in[1];
    const float* hyper_msg = (const float*)d_in[2];
    const int* ac = (const int*)d_in[ci0];
    const int* pc = (const int*)d_in[ci1];
    const int* hc = (const int*)d_in[ci2];

    const float* p2h[8];
    const float* a2p[8];
    for (int i = 0; i < 8; i++) p2h[i] = (const float*)d_in[wbase + i];
    for (int i = 0; i < 8; i++) a2p[i] = (const float*)d_in[wbase + 8 + i];
    const float* Wih_f = (const float*)d_in[wbase + 16];
    const float* Whh_f = (const float*)d_in[wbase + 17];
    const float* bih_f = (const float*)d_in[wbase + 18];
    const float* bhh_f = (const float*)d_in[wbase + 19];
    const float* Wih_b = (const float*)d_in[wbase + 20];
    const float* Whh_b = (const float*)d_in[wbase + 21];
    const float* bih_b = (const float*)d_in[wbase + 22];
    const float* bhh_b = (const float*)d_in[wbase + 23];

    float* atom_f  = symaddr(g_atom_f);
    float* pharm_f = symaddr(g_pharm_f);
    float* hyper_f = symaddr(g_hyper_f);
    float* q1 = symaddr(g_q1);
    float* k1 = symaddr(g_k1);
    float* v1 = symaddr(g_v1);
    float* o1 = symaddr(g_o1);
    float* pharm2 = symaddr(g_pharm2);
    float* q2 = symaddr(g_q2);
    float* k2 = symaddr(g_k2);
    float* v2 = symaddr(g_v2);
    float* o2 = symaddr(g_o2);
    float* hbuf = symaddr(g_h);
    float* gi_f = symaddr(g_gi_f);
    float* gi_b = symaddr(g_gi_b);

    float* out = (float*)d_out;

    const int MA = NB * TNA;   // 32512 = 254 * 128
    const int MP = NB * TNP;   // 5888  = 46  * 128
    const int MH = NB * TNH;   // 2816  = 22  * 128

    prefix_kernel<<<1, 32>>>(ac, pc, hc);

    gather_kernel<<<dim3(TNA, NB), 64>>>(atom_msg,  ac, 0, atom_f,  TNA);
    gather_kernel<<<dim3(TNP, NB), 64>>>(pharm_msg, pc, 1, pharm_f, TNP);
    gather_kernel<<<dim3(TNH, NB), 64>>>(hyper_msg, hc, 2, hyper_f, TNH);

    // MHA1 (pharm queries, hyper kv)
    bgemm_kernel<false><<<dim3(HD/64, MP/128), 256>>>(pharm_f, p2h[0], p2h[1], nullptr, q1, MP, HD, HD);
    bgemm_kernel<false><<<dim3(HD/64, MH/128), 256>>>(hyper_f, p2h[2], p2h[3], nullptr, k1, MH, HD, HD);
    bgemm_kernel<false><<<dim3(HD/64, MH/128), 256>>>(hyper_f, p2h[4], p2h[5], nullptr, v1, MH, HD, HD);
    attn_kernel<TNP, TNH><<<NB * NHEAD, 32>>>(q1, k1, v1, pc, hc, o1);
    bgemm_kernel<false><<<dim3(HD/64, MP/128), 256>>>(o1, p2h[6], p2h[7], pharm_f, pharm2, MP, HD, HD);

    // MHA2 (atom queries, updated-pharm kv)
    bgemm_kernel<false><<<dim3(HD/64, MA/128), 256>>>(atom_f, a2p[0], a2p[1], nullptr, q2, MA, HD, HD);
    bgemm_kernel<false><<<dim3(HD/64, MP/128), 256>>>(pharm2, a2p[2], a2p[3], nullptr, k2, MP, HD, HD);
    bgemm_kernel<false><<<dim3(HD/64, MP/128), 256>>>(pharm2, a2p[4], a2p[5], nullptr, v2, MP, HD, HD);
    attn_kernel<TNA, TNP><<<NB * NHEAD, 128>>>(q2, k2, v2, ac, pc, o2);
    bgemm_kernel<false><<<dim3(HD/64, MA/128), 256>>>(o2, a2p[6], a2p[7], atom_f, hbuf, MA, HD, HD);

    // h0 = max over t (both GRU directions)
    hmax_kernel<<<NB, HD>>>();

    // GRU input precompute gi = h @ Wih^T + bih (per direction)
    bgemm_kernel<true><<<dim3(G3/64, MA/128), 256>>>(hbuf, Wih_f, bih_f, nullptr, gi_f, MA, G3, HD);
    bgemm_kernel<true><<<dim3(G3/64, MA/128), 256>>>(hbuf, Wih_b, bih_b, nullptr, gi_b, MA, G3, HD);

    // GRU recurrence: per-step tensor-core GEMM + gate
    zero_outsum_kernel<<<(2 * NB * HD) / 256, 256>>>();
    for (int t = 0; t < TNA; t++) {
        gru_gh_kernel<<<dim3(G3/64, NB/128, 2), 256>>>(Whh_f, Whh_b);
        gru_gate_kernel<<<(2 * NB * HD) / 256, 256>>>(bhh_f, bhh_b, ac, t);
    }

    final_kernel<<<(2 * NB * HD) / 256, 256>>>(ac, out);
    (void)out_size; (void)n_in;
}

// round 10
// speedup vs baseline: 1.9478x; 1.1365x over previous
#include <cuda_runtime.h>
#include <cuda_bf16.h>
#include <math.h>

// ---------------------------------------------------------------------------
// HyperGraphEncoder — split-bf16 mma.sync with pre-split operands everywhere
// ---------------------------------------------------------------------------

namespace {
constexpr int NB   = 256;
constexpr int HD   = 256;
constexpr int NHEAD = 4;
constexpr int DKH  = 64;
constexpr int TNA  = 127;
constexpr int TNP  = 23;
constexpr int TNH  = 11;
constexpr int G3   = 768;
constexpr int BKP  = 40;             // padded bf16 k-stride in smem
constexpr int WPROJ = HD * HD;       // 65536
constexpr int WGRU  = G3 * HD;       // 196608
constexpr int WOFF_GRU = 8 * WPROJ;  // 524288
constexpr int WTOT = WOFF_GRU + 4 * WGRU;
}

// -------------------------- device scratch ---------------------------------
__device__ float g_atom_f [NB*TNA*HD];
__device__ float g_pharm_f[NB*TNP*HD];
__device__ float g_hyper_f[NB*TNH*HD];
__device__ float g_q1 [NB*TNP*HD];
__device__ float g_k1 [NB*TNH*HD];
__device__ float g_v1 [NB*TNH*HD];
__device__ float g_q2 [NB*TNA*HD];
__device__ float g_k2 [NB*TNP*HD];
__device__ float g_v2 [NB*TNP*HD];
__device__ float g_pharm2[NB*TNP*HD];
__device__ float g_h  [NB*TNA*HD];
__device__ float g_gi_f[(size_t)NB*TNA*G3];
__device__ float g_gi_b[(size_t)NB*TNA*G3];
__device__ float g_hcur[2*NB*HD];
__device__ float g_gh  [2*NB*G3];
__device__ float g_outsum[2*NB*HD];
__device__ int   g_starts[3*(NB+1)];

// bf16 split planes: [0] = hi, [1] = lo
__device__ __nv_bfloat16 g_atom_s [2][NB*TNA*HD];
__device__ __nv_bfloat16 g_pharm_s[2][NB*TNP*HD];
__device__ __nv_bfloat16 g_hyper_s[2][NB*TNH*HD];
__device__ __nv_bfloat16 g_o1_s   [2][NB*TNP*HD];
__device__ __nv_bfloat16 g_pharm2_s[2][NB*TNP*HD];
__device__ __nv_bfloat16 g_o2_s   [2][NB*TNA*HD];
__device__ __nv_bfloat16 g_h_s    [2][NB*TNA*HD];
__device__ __nv_bfloat16 g_hcur_s [2][2*NB*HD];
__device__ __nv_bfloat16 g_w_s    [2][WTOT];

// -------------------------- helpers ----------------------------------------
__device__ __forceinline__ unsigned s2u(const void* p) {
    return (unsigned)__cvta_generic_to_shared(p);
}
__device__ __forceinline__ void ldmx4(unsigned addr, unsigned& r0, unsigned& r1,
                                      unsigned& r2, unsigned& r3) {
    asm volatile("ldmatrix.sync.aligned.m8n8.x4.shared.b16 {%0,%1,%2,%3}, [%4];"
                 : "=r"(r0), "=r"(r1), "=r"(r2), "=r"(r3) : "r"(addr));
}
__device__ __forceinline__ void mma_bf16(float* c, unsigned a0, unsigned a1,
                                         unsigned a2, unsigned a3,
                                         unsigned b0, unsigned b1) {
    asm volatile(
        "mma.sync.aligned.m16n8k16.row.col.f32.bf16.bf16.f32 "
        "{%0,%1,%2,%3},{%4,%5,%6,%7},{%8,%9},{%0,%1,%2,%3};"
        : "+f"(c[0]), "+f"(c[1]), "+f"(c[2]), "+f"(c[3])
        : "r"(a0), "r"(a1), "r"(a2), "r"(a3), "r"(b0), "r"(b1));
}
__device__ __forceinline__ void split_bf16(float x, __nv_bfloat16& hi, __nv_bfloat16& lo) {
    hi = __float2bfloat16(x);
    lo = __float2bfloat16(x - __bfloat162float(hi));
}

// -------------------------- weight pre-split --------------------------------
// Output layout [N,K]. src_nk: source already [N,K]; else source is [K,N].
__global__ void wsplit_kernel(const float* __restrict__ W,
                              __nv_bfloat16* __restrict__ hi,
                              __nv_bfloat16* __restrict__ lo,
                              int N, int K, int src_nk) {
    int idx = blockIdx.x * 256 + threadIdx.x;
    int n = idx / K, k = idx - n * K;
    float v = src_nk ? W[idx] : W[(size_t)k * N + n];
    __nv_bfloat16 h, l;
    split_bf16(v, h, l);
    hi[idx] = h;
    lo[idx] = l;
}

// -------------------------- prefix sums ------------------------------------
__global__ void prefix_kernel(const int* __restrict__ ac,
                              const int* __restrict__ pc,
                              const int* __restrict__ hc) {
    int w = threadIdx.x;
    if (w < 3) {
        const int* c = (w == 0) ? ac : (w == 1) ? pc : hc;
        int* s = (int*)(g_starts + w * (NB + 1));
        int acc = 0;
        for (int i = 0; i < NB; i++) { s[i] = acc; acc += c[i]; }
        s[NB] = acc;
    }
}

// -------------------------- gather / zero-pad + split ------------------------
__global__ void gather_kernel(const float* __restrict__ msg,
                              const int* __restrict__ counts, int which,
                              float* __restrict__ out,
                              __nv_bfloat16* __restrict__ ohi,
                              __nv_bfloat16* __restrict__ olo, int maxN) {
    int j = blockIdx.x, b = blockIdx.y;
    int cnt = counts[b];
    size_t e = ((size_t)b * maxN + j) * HD + threadIdx.x * 4;
    float4 v = make_float4(0.f, 0.f, 0.f, 0.f);
    if (j < cnt) {
        int src_row = g_starts[which * (NB + 1) + b] + j;
        v = *(const float4*)(msg + (size_t)src_row * HD + threadIdx.x * 4);
    }
    *(float4*)(out + e) = v;
    __nv_bfloat16 h0,l0,h1,l1,h2,l2,h3,l3;
    split_bf16(v.x, h0, l0); split_bf16(v.y, h1, l1);
    split_bf16(v.z, h2, l2); split_bf16(v.w, h3, l3);
    __nv_bfloat162 ha; ha.x = h0; ha.y = h1;
    __nv_bfloat162 hb; hb.x = h2; hb.y = h3;
    __nv_bfloat162 la; la.x = l0; la.y = l1;
    __nv_bfloat162 lb; lb.x = l2; lb.y = l3;
    ((__nv_bfloat162*)(ohi + e))[0] = ha; ((__nv_bfloat162*)(ohi + e))[1] = hb;
    ((__nv_bfloat162*)(olo + e))[0] = la; ((__nv_bfloat162*)(olo + e))[1] = lb;
}

// ---------------------------------------------------------------------------
// pre-split bf16 GEMM: C[M,N] = (Ahi+Alo)[M,K] @ (Bhi+Blo)[N,K]^T (+bias)(+resid)
// Block 128M x 64N, BK=32, 256 threads (8 warps = 4m x 2n of 32x32).
// ---------------------------------------------------------------------------
__device__ __forceinline__ void bgemm_pre_body(
    const __nv_bfloat16* __restrict__ Ahi, const __nv_bfloat16* __restrict__ Alo,
    const __nv_bfloat16* __restrict__ Bhi, const __nv_bfloat16* __restrict__ Blo,
    const float* __restrict__ bias, const float* __restrict__ resid,
    float* __restrict__ C, __nv_bfloat16* __restrict__ Chi,
    __nv_bfloat16* __restrict__ Clo,
    int N, int K, int m0, int n0,
    __nv_bfloat16 (*As)[128][BKP], __nv_bfloat16 (*Bs)[64][BKP]) {

    int tid = threadIdx.x;
    int warp = tid >> 5, lane = tid & 31;
    int wm = (warp & 3) * 32;
    int wn = (warp >> 2) * 32;

    float acc[2][4][4];
#pragma unroll
    for (int i = 0; i < 2; i++)
#pragma unroll
        for (int j = 0; j < 4; j++)
#pragma unroll
            for (int r = 0; r < 4; r++) acc[i][j][r] = 0.f;

    for (int k0 = 0; k0 < K; k0 += 32) {
        // A tiles (hi+lo): 1024 uint4
#pragma unroll
        for (int l = 0; l < 4; l++) {
            int idx = tid + l * 256;
            int plane = idx >> 9, r = idx & 511;
            int row = r >> 2, c16 = r & 3;
            const __nv_bfloat16* s = (plane ? Alo : Ahi) +
                (size_t)(m0 + row) * K + k0 + c16 * 8;
            *(uint4*)&As[plane][row][c16 * 8] = *(const uint4*)s;
        }
        // B tiles (hi+lo): 512 uint4
#pragma unroll
        for (int l = 0; l < 2; l++) {
            int idx = tid + l * 256;
            int plane = idx >> 8, r = idx & 255;
            int row = r >> 2, c16 = r & 3;
            const __nv_bfloat16* s = (plane ? Blo : Bhi) +
                (size_t)(n0 + row) * K + k0 + c16 * 8;
            *(uint4*)&Bs[plane][row][c16 * 8] = *(const uint4*)s;
        }
        __syncthreads();

        int r = lane & 15, cg = lane >> 4;
#pragma unroll
        for (int kk = 0; kk < 32; kk += 16) {
            unsigned ah[2][4], al[2][4];
#pragma unroll
            for (int mf = 0; mf < 2; mf++) {
                ldmx4(s2u(&As[0][wm + mf*16 + r][kk + cg*8]),
                      ah[mf][0], ah[mf][1], ah[mf][2], ah[mf][3]);
                ldmx4(s2u(&As[1][wm + mf*16 + r][kk + cg*8]),
                      al[mf][0], al[mf][1], al[mf][2], al[mf][3]);
            }
            unsigned bh[4][2], bl[4][2];
#pragma unroll
            for (int bf = 0; bf < 2; bf++) {
                unsigned q0, q1, q2, q3;
                ldmx4(s2u(&Bs[0][wn + bf*16 + r][kk + cg*8]), q0, q1, q2, q3);
                bh[bf*2+0][0] = q0; bh[bf*2+1][0] = q1;
                bh[bf*2+0][1] = q2; bh[bf*2+1][1] = q3;
                ldmx4(s2u(&Bs[1][wn + bf*16 + r][kk + cg*8]), q0, q1, q2, q3);
                bl[bf*2+0][0] = q0; bl[bf*2+1][0] = q1;
                bl[bf*2+0][1] = q2; bl[bf*2+1][1] = q3;
            }
#pragma unroll
            for (int mf = 0; mf < 2; mf++)
#pragma unroll
                for (int nf = 0; nf < 4; nf++) {
                    mma_bf16(acc[mf][nf], ah[mf][0], ah[mf][1], ah[mf][2], ah[mf][3],
                             bh[nf][0], bh[nf][1]);
                    mma_bf16(acc[mf][nf], ah[mf][0], ah[mf][1], ah[mf][2], ah[mf][3],
                             bl[nf][0], bl[nf][1]);
                    mma_bf16(acc[mf][nf], al[mf][0], al[mf][1], al[mf][2], al[mf][3],
                             bh[nf][0], bh[nf][1]);
                }
        }
        __syncthreads();
    }

    int g = lane >> 2, tg = lane & 3;
#pragma unroll
    for (int mf = 0; mf < 2; mf++) {
#pragma unroll
        for (int nf = 0; nf < 4; nf++) {
            int c = n0 + wn + nf * 8 + tg * 2;
            int r0 = m0 + wm + mf * 16 + g;
            int r1 = r0 + 8;
            float v0 = acc[mf][nf][0], v1 = acc[mf][nf][1];
            float v2 = acc[mf][nf][2], v3 = acc[mf][nf][3];
            if (bias) { float b0 = bias[c], b1 = bias[c+1];
                        v0 += b0; v1 += b1; v2 += b0; v3 += b1; }
            if (resid) {
                float2 ra = *(const float2*)&resid[(size_t)r0 * N + c];
                float2 rb = *(const float2*)&resid[(size_t)r1 * N + c];
                v0 += ra.x; v1 += ra.y; v2 += rb.x; v3 += rb.y;
            }
            float2 oa; oa.x = v0; oa.y = v1;
            float2 ob; ob.x = v2; ob.y = v3;
            *(float2*)&C[(size_t)r0 * N + c] = oa;
            *(float2*)&C[(size_t)r1 * N + c] = ob;
            if (Chi) {
                __nv_bfloat16 h0,l0,h1,l1;
                split_bf16(v0, h0, l0); split_bf16(v1, h1, l1);
                __nv_bfloat162 hp; hp.x = h0; hp.y = h1;
                __nv_bfloat162 lp; lp.x = l0; lp.y = l1;
                *(__nv_bfloat162*)&Chi[(size_t)r0 * N + c] = hp;
                *(__nv_bfloat162*)&Clo[(size_t)r0 * N + c] = lp;
                split_bf16(v2, h0, l0); split_bf16(v3, h1, l1);
                hp.x = h0; hp.y = h1; lp.x = l0; lp.y = l1;
                *(__nv_bfloat162*)&Chi[(size_t)r1 * N + c] = hp;
                *(__nv_bfloat162*)&Clo[(size_t)r1 * N + c] = lp;
            }
        }
    }
}

__global__ void __launch_bounds__(256)
bgemm_pre_kernel(const __nv_bfloat16* __restrict__ Ahi, const __nv_bfloat16* __restrict__ Alo,
                 const __nv_bfloat16* __restrict__ Bhi, const __nv_bfloat16* __restrict__ Blo,
                 const float* __restrict__ bias, const float* __restrict__ resid,
                 float* __restrict__ C, __nv_bfloat16* __restrict__ Chi,
                 __nv_bfloat16* __restrict__ Clo, int N, int K) {
    __shared__ __nv_bfloat16 As[2][128][BKP];
    __shared__ __nv_bfloat16 Bs[2][64][BKP];
    bgemm_pre_body(Ahi, Alo, Bhi, Blo, bias, resid, C, Chi, Clo,
                   N, K, blockIdx.y * 128, blockIdx.x * 64, As, Bs);
}

// GRU recurrent GEMM: gh[d] = hcur[d] @ Whh_d^T   (M=256/dir, N=768, K=256)
// grid (12, 2, 2)
__global__ void __launch_bounds__(256)
gru_gh_kernel() {
    __shared__ __nv_bfloat16 As[2][128][BKP];
    __shared__ __nv_bfloat16 Bs[2][64][BKP];
    int d = blockIdx.z;
    size_t hoff = (size_t)d * NB * HD;
    size_t woff = WOFF_GRU + (d ? 3 : 1) * (size_t)WGRU;   // Whh_f at +1, Whh_b at +3
    bgemm_pre_body(g_hcur_s[0] + hoff, g_hcur_s[1] + hoff,
                   g_w_s[0] + woff, g_w_s[1] + woff,
                   nullptr, nullptr,
                   g_gh + (size_t)d * NB * G3, nullptr, nullptr,
                   G3, HD, blockIdx.y * 128, blockIdx.x * 64, As, Bs);
}

// -------------------------- attention (fp32 in, split out) -------------------
template <int LQ, int LK>
__global__ void attn_kernel(const float* __restrict__ qh,
                            const float* __restrict__ kh,
                            const float* __restrict__ vh,
                            const int* __restrict__ qc,
                            const int* __restrict__ kc,
                            __nv_bfloat16* __restrict__ ohi,
                            __nv_bfloat16* __restrict__ olo) {
    __shared__ float ks[LK * DKH];
    __shared__ float vs[LK * DKH];
    int bh = blockIdx.x;
    int b = bh / NHEAD, hd = bh % NHEAD;
    for (int idx = threadIdx.x; idx < LK * DKH; idx += blockDim.x) {
        int k = idx / DKH, i = idx % DKH;
        size_t base = ((size_t)(b * LK) + k) * HD + hd * DKH + i;
        ks[idx] = kh[base];
        vs[idx] = vh[base];
    }
    __syncthreads();
    int q = threadIdx.x;
    if (q >= LQ) return;

    float qreg[DKH];
    const float* qp = &qh[((size_t)(b * LQ) + q) * HD + hd * DKH];
#pragma unroll
    for (int i = 0; i < DKH; i++) qreg[i] = qp[i];

    bool vq = q < qc[b];
    int kcnt = kc[b];
    float s[LK];
    float mx = -3.402823e38f;
#pragma unroll
    for (int k = 0; k < LK; k++) {
        float d = 0.f;
#pragma unroll
        for (int i = 0; i < DKH; i++) d = fmaf(qreg[i], ks[k * DKH + i], d);
        float val = (vq && k < kcnt) ? d * 0.125f : -1e9f;
        s[k] = val;
        mx = fmaxf(mx, val);
    }
    float sum = 0.f;
#pragma unroll
    for (int k = 0; k < LK; k++) { s[k] = expf(s[k] - mx); sum += s[k]; }
    float inv = 1.f / sum;
    size_t obase = ((size_t)(b * LQ) + q) * HD + hd * DKH;
#pragma unroll
    for (int i = 0; i < DKH; i++) {
        float a = 0.f;
#pragma unroll
        for (int k = 0; k < LK; k++) a = fmaf(s[k], vs[k * DKH + i], a);
        a *= inv;
        __nv_bfloat16 h, l;
        split_bf16(a, h, l);
        ohi[obase + i] = h;
        olo[obase + i] = l;
    }
}

// -------------------------- h0 = max over t (+ split) ------------------------
__global__ void hmax_kernel() {
    int b = blockIdx.x, j = threadIdx.x;
    float m = -3.402823e38f;
    for (int t = 0; t < TNA; t++)
        m = fmaxf(m, g_h[((size_t)(b * TNA) + t) * HD + j]);
    size_t i0 = (size_t)b * HD + j;
    size_t i1 = (size_t)NB * HD + i0;
    g_hcur[i0] = m; g_hcur[i1] = m;
    __nv_bfloat16 h, l;
    split_bf16(m, h, l);
    g_hcur_s[0][i0] = h; g_hcur_s[0][i1] = h;
    g_hcur_s[1][i0] = l; g_hcur_s[1][i1] = l;
}

__global__ void zero_outsum_kernel() {
    int idx = blockIdx.x * blockDim.x + threadIdx.x;
    g_outsum[idx] = 0.f;
}

// -------------------------- GRU gate update (+ split hcur) -------------------
__global__ void __launch_bounds__(256)
gru_gate_kernel(const float* __restrict__ bhh_f, const float* __restrict__ bhh_b,
                const int* __restrict__ counts, int t) {
    int idx = blockIdx.x * blockDim.x + threadIdx.x;
    int d = idx >> 16;
    int b = (idx >> 8) & 255;
    int j = idx & 255;
    int teff = d ? (TNA - 1 - t) : t;
    const float* gi = (d ? g_gi_b : g_gi_f) + ((size_t)(b * TNA) + teff) * G3;
    const float* bhh = d ? bhh_b : bhh_f;
    const float* gh = g_gh + (size_t)d * NB * G3 + (size_t)b * G3;
    float ir = gi[j], iz = gi[j + 256], in = gi[j + 512];
    float hr = gh[j] + bhh[j];
    float hz = gh[j + 256] + bhh[j + 256];
    float hn = gh[j + 512] + bhh[j + 512];
    float r = 1.f / (1.f + expf(-(ir + hr)));
    float z = 1.f / (1.f + expf(-(iz + hz)));
    float n = tanhf(in + r * hn);
    size_t hidx = (size_t)d * NB * HD + (size_t)b * HD + j;
    float hp = g_hcur[hidx];
    float h = (1.f - z) * n + z * hp;
    g_hcur[hidx] = h;
    __nv_bfloat16 hh, hl;
    split_bf16(h, hh, hl);
    g_hcur_s[0][hidx] = hh;
    g_hcur_s[1][hidx] = hl;
    if (teff < counts[b]) g_outsum[hidx] += h;
}

__global__ void final_kernel(const int* __restrict__ counts, float* __restrict__ out) {
    int idx = blockIdx.x * blockDim.x + threadIdx.x;
    int d = idx >> 16;
    int b = (idx >> 8) & 255;
    int j = idx & 255;
    float c = (float)counts[b];
    out[(size_t)b * 512 + d * 256 + j] =
        g_outsum[(size_t)d * NB * HD + (size_t)b * HD + j] / c;
}

// -------------------------- host launch -------------------------------------
template <typename T>
static T* symaddr(const void* sym) {
    void* p = nullptr;
    cudaGetSymbolAddress(&p, sym);
    return (T*)p;
}

extern "C" void kernel_launch(void* const* d_in, const int* in_sizes, int n_in,
                              void* d_out, int out_size) {
    int wbase, ci0, ci1, ci2;
    if (in_sizes[3] == NB) { ci0 = 3; ci1 = 4; ci2 = 5; wbase = 6; }
    else { wbase = 3; ci0 = n_in - 3; ci1 = n_in - 2; ci2 = n_in - 1; }

    const float* atom_msg  = (const float*)d_in[0];
    const float* pharm_msg = (const float*)d_in[1];
    const float* hyper_msg = (const float*)d_in[2];
    const int* ac = (const int*)d_in[ci0];
    const int* pc = (const int*)d_in[ci1];
    const int* hc = (const int*)d_in[ci2];

    const float* p2h[8];
    const float* a2p[8];
    for (int i = 0; i < 8; i++) p2h[i] = (const float*)d_in[wbase + i];
    for (int i = 0; i < 8; i++) a2p[i] = (const float*)d_in[wbase + 8 + i];
    const float* Wih_f = (const float*)d_in[wbase + 16];
    const float* Whh_f = (const float*)d_in[wbase + 17];
    const float* bih_f = (const float*)d_in[wbase + 18];
    const float* bhh_f = (const float*)d_in[wbase + 19];
    const float* Wih_b = (const float*)d_in[wbase + 20];
    const float* Whh_b = (const float*)d_in[wbase + 21];
    const float* bih_b = (const float*)d_in[wbase + 22];
    const float* bhh_b = (const float*)d_in[wbase + 23];

    float* atom_f  = symaddr<float>(g_atom_f);
    float* pharm_f = symaddr<float>(g_pharm_f);
    float* hyper_f = symaddr<float>(g_hyper_f);
    float* q1 = symaddr<float>(g_q1);
    float* k1 = symaddr<float>(g_k1);
    float* v1 = symaddr<float>(g_v1);
    float* q2 = symaddr<float>(g_q2);
    float* k2 = symaddr<float>(g_k2);
    float* v2 = symaddr<float>(g_v2);
    float* pharm2 = symaddr<float>(g_pharm2);
    float* hbuf = symaddr<float>(g_h);
    float* gi_f = symaddr<float>(g_gi_f);
    float* gi_b = symaddr<float>(g_gi_b);

    __nv_bfloat16* atom_s  = symaddr<__nv_bfloat16>(g_atom_s);
    __nv_bfloat16* pharm_s = symaddr<__nv_bfloat16>(g_pharm_s);
    __nv_bfloat16* hyper_s = symaddr<__nv_bfloat16>(g_hyper_s);
    __nv_bfloat16* o1_s    = symaddr<__nv_bfloat16>(g_o1_s);
    __nv_bfloat16* pharm2_s= symaddr<__nv_bfloat16>(g_pharm2_s);
    __nv_bfloat16* o2_s    = symaddr<__nv_bfloat16>(g_o2_s);
    __nv_bfloat16* h_s     = symaddr<__nv_bfloat16>(g_h_s);
    __nv_bfloat16* w_s     = symaddr<__nv_bfloat16>(g_w_s);

    const size_t SA = (size_t)NB*TNA*HD;
    const size_t SP = (size_t)NB*TNP*HD;
    const size_t SH = (size_t)NB*TNH*HD;
    __nv_bfloat16 *atom_hi = atom_s,   *atom_lo = atom_s + SA;
    __nv_bfloat16 *pharm_hi = pharm_s, *pharm_lo = pharm_s + SP;
    __nv_bfloat16 *hyper_hi = hyper_s, *hyper_lo = hyper_s + SH;
    __nv_bfloat16 *o1_hi = o1_s,       *o1_lo = o1_s + SP;
    __nv_bfloat16 *pharm2_hi = pharm2_s, *pharm2_lo = pharm2_s + SP;
    __nv_bfloat16 *o2_hi = o2_s,       *o2_lo = o2_s + SA;
    __nv_bfloat16 *h_hi = h_s,         *h_lo = h_s + SA;
    __nv_bfloat16 *w_hi = w_s,         *w_lo = w_s + WTOT;

    float* out = (float*)d_out;

    const int MA = NB * TNA;   // 32512 = 254*128
    const int MP = NB * TNP;   // 5888  = 46*128
    const int MH = NB * TNH;   // 2816  = 22*128

    prefix_kernel<<<1, 32>>>(ac, pc, hc);

    // ---- pre-split weights ----
    for (int i = 0; i < 4; i++)
        wsplit_kernel<<<WPROJ/256, 256>>>(p2h[2*i], w_hi + (size_t)i*WPROJ,
                                          w_lo + (size_t)i*WPROJ, HD, HD, 0);
    for (int i = 0; i < 4; i++)
        wsplit_kernel<<<WPROJ/256, 256>>>(a2p[2*i], w_hi + (size_t)(4+i)*WPROJ,
                                          w_lo + (size_t)(4+i)*WPROJ, HD, HD, 0);
    const float* gw[4] = {Wih_f, Whh_f, Wih_b, Whh_b};
    for (int i = 0; i < 4; i++)
        wsplit_kernel<<<WGRU/256, 256>>>(gw[i], w_hi + WOFF_GRU + (size_t)i*WGRU,
                                         w_lo + WOFF_GRU + (size_t)i*WGRU, G3, HD, 1);

    // ---- gathers (+split) ----
    gather_kernel<<<dim3(TNA, NB), 64>>>(atom_msg,  ac, 0, atom_f,  atom_hi,  atom_lo,  TNA);
    gather_kernel<<<dim3(TNP, NB), 64>>>(pharm_msg, pc, 1, pharm_f, pharm_hi, pharm_lo, TNP);
    gather_kernel<<<dim3(TNH, NB), 64>>>(hyper_msg, hc, 2, hyper_f, hyper_hi, hyper_lo, TNH);

    // ---- MHA1 ----
    bgemm_pre_kernel<<<dim3(HD/64, MP/128), 256>>>(pharm_hi, pharm_lo,
        w_hi + 0*WPROJ, w_lo + 0*WPROJ, p2h[1], nullptr, q1, nullptr, nullptr, HD, HD);
    bgemm_pre_kernel<<<dim3(HD/64, MH/128), 256>>>(hyper_hi, hyper_lo,
        w_hi + 1*WPROJ, w_lo + 1*WPROJ, p2h[3], nullptr, k1, nullptr, nullptr, HD, HD);
    bgemm_pre_kernel<<<dim3(HD/64, MH/128), 256>>>(hyper_hi, hyper_lo,
        w_hi + 2*WPROJ, w_lo + 2*WPROJ, p2h[5], nullptr, v1, nullptr, nullptr, HD, HD);
    attn_kernel<TNP, TNH><<<NB * NHEAD, 32>>>(q1, k1, v1, pc, hc, o1_hi, o1_lo);
    bgemm_pre_kernel<<<dim3(HD/64, MP/128), 256>>>(o1_hi, o1_lo,
        w_hi + 3*WPROJ, w_lo + 3*WPROJ, p2h[7], pharm_f, pharm2, pharm2_hi, pharm2_lo, HD, HD);

    // ---- MHA2 ----
    bgemm_pre_kernel<<<dim3(HD/64, MA/128), 256>>>(atom_hi, atom_lo,
        w_hi + 4*WPROJ, w_lo + 4*WPROJ, a2p[1], nullptr, q2, nullptr, nullptr, HD, HD);
    bgemm_pre_kernel<<<dim3(HD/64, MP/128), 256>>>(pharm2_hi, pharm2_lo,
        w_hi + 5*WPROJ, w_lo + 5*WPROJ, a2p[3], nullptr, k2, nullptr, nullptr, HD, HD);
    bgemm_pre_kernel<<<dim3(HD/64, MP/128), 256>>>(pharm2_hi, pharm2_lo,
        w_hi + 6*WPROJ, w_lo + 6*WPROJ, a2p[5], nullptr, v2, nullptr, nullptr, HD, HD);
    attn_kernel<TNA, TNP><<<NB * NHEAD, 128>>>(q2, k2, v2, ac, pc, o2_hi, o2_lo);
    bgemm_pre_kernel<<<dim3(HD/64, MA/128), 256>>>(o2_hi, o2_lo,
        w_hi + 7*WPROJ, w_lo + 7*WPROJ, a2p[7], atom_f, hbuf, h_hi, h_lo, HD, HD);

    // ---- h0 = max over t ----
    hmax_kernel<<<NB, HD>>>();

    // ---- gi = h @ Wih^T + bih ----
    bgemm_pre_kernel<<<dim3(G3/64, MA/128), 256>>>(h_hi, h_lo,
        w_hi + WOFF_GRU + 0*WGRU, w_lo + WOFF_GRU + 0*WGRU, bih_f, nullptr,
        gi_f, nullptr, nullptr, G3, HD);
    bgemm_pre_kernel<<<dim3(G3/64, MA/128), 256>>>(h_hi, h_lo,
        w_hi + WOFF_GRU + 2*WGRU, w_lo + WOFF_GRU + 2*WGRU, bih_b, nullptr,
        gi_b, nullptr, nullptr, G3, HD);

    // ---- GRU recurrence ----
    zero_outsum_kernel<<<(2 * NB * HD) / 256, 256>>>();
    for (int t = 0; t < TNA; t++) {
        gru_gh_kernel<<<dim3(G3/64, 2, 2), 256>>>();
        gru_gate_kernel<<<(2 * NB * HD) / 256, 256>>>(bhh_f, bhh_b, ac, t);
    }

    final_kernel<<<(2 * NB * HD) / 256, 256>>>(ac, out);
    (void)out_size; (void)n_in;
}